// round 14
// baseline (speedup 1.0000x reference)
#include <cuda_runtime.h>
#include <cuda_bf16.h>
#include <math.h>

// Problem constants (fixed shapes)
#define BB 4
#define HH 1024
#define WW 1920
#define HW (HH * WW)                 // 1,966,080
#define NPIX (BB * HW)               // 7,864,320
#define ALPHA 100.0f
#define EPSN 1e-7f

// Scratch accumulator: [B][H][W][4] channel-interleaved, 16B/pixel (~126 MB).
// Zero-initialized at module load; normalize_kernel re-zeros it every call,
// so every kernel_launch invocation (correctness run + each graph replay)
// starts from a zeroed accumulator without a separate memset pass.
__device__ __align__(16) float g_acc[(size_t)NPIX * 4];

// ---------------------------------------------------------------------------
// Splat kernel: 1 thread = 1 pixel (latency-optimized; max warp parallelism).
// ---------------------------------------------------------------------------
__global__ void __launch_bounds__(256)
splat_metric_kernel(const float* __restrict__ rgb1,
                    const float* __restrict__ rgb2,
                    const float* __restrict__ flow_t,
                    const float* __restrict__ flow12,
                    float* __restrict__ out_metric)
{
    int i = blockIdx.x * blockDim.x + threadIdx.x;
    if (i >= NPIX) return;

    int b   = i / HW;
    int rem = i - b * HW;
    int y   = rem / WW;
    int x   = rem - y * WW;

    // ---- Backwarp rgb2 with flow12 (bilinear gather, zeros padding) ----
    const float* f12 = flow12 + (size_t)b * 2 * HW;
    float px = (float)x + f12[rem];
    float py = (float)y + f12[HW + rem];
    float x0f = floorf(px), y0f = floorf(py);
    int   x0  = (int)x0f,   y0  = (int)y0f;
    float wx  = px - x0f,   wy  = py - y0f;

    const float* r2 = rgb2 + (size_t)b * 3 * HW;
    float bw0 = 0.f, bw1 = 0.f, bw2 = 0.f;
    {
        float wtx[2] = {1.f - wx, wx};
        float wty[2] = {1.f - wy, wy};
        #pragma unroll
        for (int ty = 0; ty < 2; ty++) {
            int yi = y0 + ty;
            if (yi < 0 || yi >= HH) continue;
            #pragma unroll
            for (int tx = 0; tx < 2; tx++) {
                int xi = x0 + tx;
                if (xi < 0 || xi >= WW) continue;
                float w   = wtx[tx] * wty[ty];
                int   idx = yi * WW + xi;
                bw0 += w * __ldg(r2 + idx);
                bw1 += w * __ldg(r2 + HW + idx);
                bw2 += w * __ldg(r2 + 2 * HW + idx);
            }
        }
    }

    // ---- Metric (channel-mean L1) + splat weight ----
    const float* r1 = rgb1 + (size_t)b * 3 * HW;
    float c0 = r1[rem];
    float c1 = r1[HW + rem];
    float c2 = r1[2 * HW + rem];
    float metric = (fabsf(c0 - bw0) + fabsf(c1 - bw1) + fabsf(c2 - bw2)) * (1.0f / 3.0f);
    out_metric[i] = metric;

    float m  = fminf(fmaxf(-ALPHA * metric, -ALPHA), ALPHA);
    float em = __expf(m);

    // ---- Forward splat (bilinear scatter-add) with flow_t ----
    const float* ft = flow_t + (size_t)b * 2 * HW;
    float qx = (float)x + ft[rem];
    float qy = (float)y + ft[HW + rem];
    float qx0f = floorf(qx), qy0f = floorf(qy);
    int   qx0  = (int)qx0f,  qy0  = (int)qy0f;
    float ux   = qx - qx0f,  uy   = qy - qy0f;

    float v0 = c0 * em, v1 = c1 * em, v2 = c2 * em;
    float* acc = g_acc + (size_t)b * HW * 4;

    float utx[2] = {1.f - ux, ux};
    float uty[2] = {1.f - uy, uy};
    #pragma unroll
    for (int ty = 0; ty < 2; ty++) {
        int yi = qy0 + ty;
        if (yi < 0 || yi >= HH) continue;
        #pragma unroll
        for (int tx = 0; tx < 2; tx++) {
            int xi = qx0 + tx;
            if (xi < 0 || xi >= WW) continue;
            float w = utx[tx] * uty[ty];
            float4* p = (float4*)(acc + (size_t)(yi * WW + xi) * 4);
            atomicAdd(p, make_float4(v0 * w, v1 * w, v2 * w, em * w));
        }
    }
}

// ---------------------------------------------------------------------------
// Normalize kernel: 1 thread = 1 pixel (coalesced float4 per lane).
// Re-zeros the accumulator in place of a separate memset pass.
// ---------------------------------------------------------------------------
__global__ void __launch_bounds__(256)
normalize_kernel(float* __restrict__ out_img)
{
    int i = blockIdx.x * blockDim.x + threadIdx.x;
    if (i >= NPIX) return;

    float4* accp = (float4*)(g_acc + (size_t)i * 4);
    float4 v = *accp;
    *accp = make_float4(0.f, 0.f, 0.f, 0.f);   // zero for next invocation

    float inv = 1.0f / (v.w + EPSN);

    int b   = i / HW;
    int rem = i - b * HW;
    float* o = out_img + (size_t)b * 3 * HW;
    o[rem]          = v.x * inv;
    o[HW + rem]     = v.y * inv;
    o[2 * HW + rem] = v.z * inv;
}

extern "C" void kernel_launch(void* const* d_in, const int* in_sizes, int n_in,
                              void* d_out, int out_size)
{
    const float* rgb1   = (const float*)d_in[0];
    const float* rgb2   = (const float*)d_in[1];
    const float* flow_t = (const float*)d_in[2];  // flow_src1_to_tgt
    const float* flow12 = (const float*)d_in[3];  // flow_src1_to_src2

    float* out_img    = (float*)d_out;                        // [B,3,H,W]
    float* out_metric = (float*)d_out + (size_t)BB * 3 * HW;  // [B,1,H,W]

    const int threads = 256;
    const int blocks  = (NPIX + threads - 1) / threads;

    splat_metric_kernel<<<blocks, threads, 0, 0>>>(rgb1, rgb2, flow_t, flow12, out_metric);
    normalize_kernel<<<blocks, threads, 0, 0>>>(out_img);
}

// round 15
// speedup vs baseline: 1.7050x; 1.7050x over previous
#include <cuda_runtime.h>
#include <cuda_bf16.h>
#include <math.h>

// Problem constants (fixed shapes)
#define BB 4
#define HH 1024
#define WW 1920
#define HW (HH * WW)                 // 1,966,080
#define NPIX (BB * HW)               // 7,864,320
#define ALPHA 100.0f
#define EPSN 1e-7f

// Scratch: splat accumulator [B][H][W][4] (RGB*em, em), 16B/pixel (~126 MB)
__device__ __align__(16) float g_acc[(size_t)NPIX * 4];
// Scratch: rgb2 packed as RGBX float4 per pixel (~126 MB) for vector gathers
__device__ __align__(16) float4 g_rgbx[(size_t)NPIX];

// ---------------------------------------------------------------------------
// Prologue (writer-only): zero the accumulator and pack rgb2 planes -> RGBX.
// No same-address load/store pairs (avoids the R14 WAR serialization).
// ---------------------------------------------------------------------------
__global__ void __launch_bounds__(256)
prologue_kernel(const float* __restrict__ rgb2)
{
    int i = blockIdx.x * blockDim.x + threadIdx.x;
    if (i >= NPIX) return;

    int b   = i / HW;
    int rem = i - b * HW;
    const float* r2 = rgb2 + (size_t)b * 3 * HW;

    g_rgbx[i] = make_float4(r2[rem], r2[HW + rem], r2[2 * HW + rem], 0.f);
    ((float4*)g_acc)[i] = make_float4(0.f, 0.f, 0.f, 0.f);
}

// ---------------------------------------------------------------------------
// Splat kernel: 1 thread = 1 pixel. Bilinear gather from packed RGBX
// (4 x LDG.128 instead of 12 x LDG.32), then bilinear scatter via RED.128.
// ---------------------------------------------------------------------------
__global__ void __launch_bounds__(256)
splat_metric_kernel(const float* __restrict__ rgb1,
                    const float* __restrict__ flow_t,
                    const float* __restrict__ flow12,
                    float* __restrict__ out_metric)
{
    int i = blockIdx.x * blockDim.x + threadIdx.x;
    if (i >= NPIX) return;

    int b   = i / HW;
    int rem = i - b * HW;
    int y   = rem / WW;
    int x   = rem - y * WW;

    // ---- Backwarp gather from packed rgb2 (bilinear, zeros padding) ----
    const float* f12 = flow12 + (size_t)b * 2 * HW;
    float px = (float)x + f12[rem];
    float py = (float)y + f12[HW + rem];
    float x0f = floorf(px), y0f = floorf(py);
    int   x0  = (int)x0f,   y0  = (int)y0f;
    float wx  = px - x0f,   wy  = py - y0f;

    const float4* rx = g_rgbx + (size_t)b * HW;
    float bw0 = 0.f, bw1 = 0.f, bw2 = 0.f;
    {
        float wtx[2] = {1.f - wx, wx};
        float wty[2] = {1.f - wy, wy};
        #pragma unroll
        for (int ty = 0; ty < 2; ty++) {
            int yi = y0 + ty;
            int yc = min(max(yi, 0), HH - 1);
            bool vy = (yi >= 0) & (yi < HH);
            #pragma unroll
            for (int tx = 0; tx < 2; tx++) {
                int xi = x0 + tx;
                int xc = min(max(xi, 0), WW - 1);
                bool v = vy & (xi >= 0) & (xi < WW);
                float w = wtx[tx] * wty[ty] * (v ? 1.f : 0.f);
                float4 g = __ldg(rx + (yc * WW + xc));
                bw0 += w * g.x;
                bw1 += w * g.y;
                bw2 += w * g.z;
            }
        }
    }

    // ---- Metric (channel-mean L1) + splat weight ----
    const float* r1 = rgb1 + (size_t)b * 3 * HW;
    float c0 = r1[rem];
    float c1 = r1[HW + rem];
    float c2 = r1[2 * HW + rem];
    float metric = (fabsf(c0 - bw0) + fabsf(c1 - bw1) + fabsf(c2 - bw2)) * (1.0f / 3.0f);
    out_metric[i] = metric;

    float m  = fminf(fmaxf(-ALPHA * metric, -ALPHA), ALPHA);
    float em = __expf(m);

    // ---- Forward splat (bilinear scatter-add) with flow_t ----
    const float* ft = flow_t + (size_t)b * 2 * HW;
    float qx = (float)x + ft[rem];
    float qy = (float)y + ft[HW + rem];
    float qx0f = floorf(qx), qy0f = floorf(qy);
    int   qx0  = (int)qx0f,  qy0  = (int)qy0f;
    float ux   = qx - qx0f,  uy   = qy - qy0f;

    float v0 = c0 * em, v1 = c1 * em, v2 = c2 * em;
    float* acc = g_acc + (size_t)b * HW * 4;

    float utx[2] = {1.f - ux, ux};
    float uty[2] = {1.f - uy, uy};
    #pragma unroll
    for (int ty = 0; ty < 2; ty++) {
        int yi = qy0 + ty;
        if (yi < 0 || yi >= HH) continue;
        #pragma unroll
        for (int tx = 0; tx < 2; tx++) {
            int xi = qx0 + tx;
            if (xi < 0 || xi >= WW) continue;
            float w = utx[tx] * uty[ty];
            float4* p = (float4*)(acc + (size_t)(yi * WW + xi) * 4);
            atomicAdd(p, make_float4(v0 * w, v1 * w, v2 * w, em * w));
        }
    }
}

// ---------------------------------------------------------------------------
// Normalize kernel: 1 thread = 1 pixel, read-only on g_acc (R9 version, 34us).
// ---------------------------------------------------------------------------
__global__ void __launch_bounds__(256)
normalize_kernel(float* __restrict__ out_img)
{
    int i = blockIdx.x * blockDim.x + threadIdx.x;
    if (i >= NPIX) return;

    float4 v = *(const float4*)(g_acc + (size_t)i * 4);
    float inv = 1.0f / (v.w + EPSN);

    int b   = i / HW;
    int rem = i - b * HW;
    float* o = out_img + (size_t)b * 3 * HW;
    o[rem]          = v.x * inv;
    o[HW + rem]     = v.y * inv;
    o[2 * HW + rem] = v.z * inv;
}

extern "C" void kernel_launch(void* const* d_in, const int* in_sizes, int n_in,
                              void* d_out, int out_size)
{
    const float* rgb1   = (const float*)d_in[0];
    const float* rgb2   = (const float*)d_in[1];
    const float* flow_t = (const float*)d_in[2];  // flow_src1_to_tgt
    const float* flow12 = (const float*)d_in[3];  // flow_src1_to_src2

    float* out_img    = (float*)d_out;                        // [B,3,H,W]
    float* out_metric = (float*)d_out + (size_t)BB * 3 * HW;  // [B,1,H,W]

    const int threads = 256;
    const int blocks  = (NPIX + threads - 1) / threads;

    prologue_kernel<<<blocks, threads, 0, 0>>>(rgb2);
    splat_metric_kernel<<<blocks, threads, 0, 0>>>(rgb1, flow_t, flow12, out_metric);
    normalize_kernel<<<blocks, threads, 0, 0>>>(out_img);
}

// round 16
// speedup vs baseline: 1.7320x; 1.0158x over previous
#include <cuda_runtime.h>
#include <cuda_bf16.h>
#include <math.h>

// Problem constants (fixed shapes)
#define BB 4
#define HH 1024
#define WW 1920
#define HW (HH * WW)                 // 1,966,080
#define NPIX (BB * HW)               // 7,864,320
#define ALPHA 100.0f
#define EPSN 1e-7f

// Scratch: splat accumulator [B][H][W][4] (RGB*em, em), 16B/pixel (~126 MB)
__device__ __align__(16) float g_acc[(size_t)NPIX * 4];
// Scratch: rgb2 packed as RGBX float4 per pixel (~126 MB) for vector gathers
__device__ __align__(16) float4 g_rgbx[(size_t)NPIX];

// ---------------------------------------------------------------------------
// Prologue (writer-only): zero the accumulator and pack rgb2 planes -> RGBX.
// No same-address load/store pairs (avoids the R14 WAR serialization).
// ---------------------------------------------------------------------------
__global__ void __launch_bounds__(256)
prologue_kernel(const float* __restrict__ rgb2)
{
    int i = blockIdx.x * blockDim.x + threadIdx.x;
    if (i >= NPIX) return;

    int b   = i / HW;
    int rem = i - b * HW;
    const float* r2 = rgb2 + (size_t)b * 3 * HW;

    g_rgbx[i] = make_float4(r2[rem], r2[HW + rem], r2[2 * HW + rem], 0.f);
    ((float4*)g_acc)[i] = make_float4(0.f, 0.f, 0.f, 0.f);
}

// ---------------------------------------------------------------------------
// Splat kernel: 1 thread = 1 pixel. Bilinear gather from packed RGBX
// (4 x LDG.128 instead of 12 x LDG.32), then bilinear scatter via RED.128.
// ---------------------------------------------------------------------------
__global__ void __launch_bounds__(256)
splat_metric_kernel(const float* __restrict__ rgb1,
                    const float* __restrict__ flow_t,
                    const float* __restrict__ flow12,
                    float* __restrict__ out_metric)
{
    int i = blockIdx.x * blockDim.x + threadIdx.x;
    if (i >= NPIX) return;

    int b   = i / HW;
    int rem = i - b * HW;
    int y   = rem / WW;
    int x   = rem - y * WW;

    // ---- Backwarp gather from packed rgb2 (bilinear, zeros padding) ----
    const float* f12 = flow12 + (size_t)b * 2 * HW;
    float px = (float)x + f12[rem];
    float py = (float)y + f12[HW + rem];
    float x0f = floorf(px), y0f = floorf(py);
    int   x0  = (int)x0f,   y0  = (int)y0f;
    float wx  = px - x0f,   wy  = py - y0f;

    const float4* rx = g_rgbx + (size_t)b * HW;
    float bw0 = 0.f, bw1 = 0.f, bw2 = 0.f;
    {
        float wtx[2] = {1.f - wx, wx};
        float wty[2] = {1.f - wy, wy};
        #pragma unroll
        for (int ty = 0; ty < 2; ty++) {
            int yi = y0 + ty;
            int yc = min(max(yi, 0), HH - 1);
            bool vy = (yi >= 0) & (yi < HH);
            #pragma unroll
            for (int tx = 0; tx < 2; tx++) {
                int xi = x0 + tx;
                int xc = min(max(xi, 0), WW - 1);
                bool v = vy & (xi >= 0) & (xi < WW);
                float w = wtx[tx] * wty[ty] * (v ? 1.f : 0.f);
                float4 g = __ldg(rx + (yc * WW + xc));
                bw0 += w * g.x;
                bw1 += w * g.y;
                bw2 += w * g.z;
            }
        }
    }

    // ---- Metric (channel-mean L1) + splat weight ----
    const float* r1 = rgb1 + (size_t)b * 3 * HW;
    float c0 = r1[rem];
    float c1 = r1[HW + rem];
    float c2 = r1[2 * HW + rem];
    float metric = (fabsf(c0 - bw0) + fabsf(c1 - bw1) + fabsf(c2 - bw2)) * (1.0f / 3.0f);
    out_metric[i] = metric;

    float m  = fminf(fmaxf(-ALPHA * metric, -ALPHA), ALPHA);
    float em = __expf(m);

    // ---- Forward splat (bilinear scatter-add) with flow_t ----
    const float* ft = flow_t + (size_t)b * 2 * HW;
    float qx = (float)x + ft[rem];
    float qy = (float)y + ft[HW + rem];
    float qx0f = floorf(qx), qy0f = floorf(qy);
    int   qx0  = (int)qx0f,  qy0  = (int)qy0f;
    float ux   = qx - qx0f,  uy   = qy - qy0f;

    float v0 = c0 * em, v1 = c1 * em, v2 = c2 * em;
    float* acc = g_acc + (size_t)b * HW * 4;

    float utx[2] = {1.f - ux, ux};
    float uty[2] = {1.f - uy, uy};
    #pragma unroll
    for (int ty = 0; ty < 2; ty++) {
        int yi = qy0 + ty;
        if (yi < 0 || yi >= HH) continue;
        #pragma unroll
        for (int tx = 0; tx < 2; tx++) {
            int xi = qx0 + tx;
            if (xi < 0 || xi >= WW) continue;
            float w = utx[tx] * uty[ty];
            float4* p = (float4*)(acc + (size_t)(yi * WW + xi) * 4);
            atomicAdd(p, make_float4(v0 * w, v1 * w, v2 * w, em * w));
        }
    }
}

// ---------------------------------------------------------------------------
// Normalize kernel: 1 thread = 1 pixel, read-only on g_acc (R9 version, 34us).
// ---------------------------------------------------------------------------
__global__ void __launch_bounds__(256)
normalize_kernel(float* __restrict__ out_img)
{
    int i = blockIdx.x * blockDim.x + threadIdx.x;
    if (i >= NPIX) return;

    float4 v = *(const float4*)(g_acc + (size_t)i * 4);
    float inv = 1.0f / (v.w + EPSN);

    int b   = i / HW;
    int rem = i - b * HW;
    float* o = out_img + (size_t)b * 3 * HW;
    o[rem]          = v.x * inv;
    o[HW + rem]     = v.y * inv;
    o[2 * HW + rem] = v.z * inv;
}

extern "C" void kernel_launch(void* const* d_in, const int* in_sizes, int n_in,
                              void* d_out, int out_size)
{
    const float* rgb1   = (const float*)d_in[0];
    const float* rgb2   = (const float*)d_in[1];
    const float* flow_t = (const float*)d_in[2];  // flow_src1_to_tgt
    const float* flow12 = (const float*)d_in[3];  // flow_src1_to_src2

    float* out_img    = (float*)d_out;                        // [B,3,H,W]
    float* out_metric = (float*)d_out + (size_t)BB * 3 * HW;  // [B,1,H,W]

    const int threads = 256;
    const int blocks  = (NPIX + threads - 1) / threads;

    prologue_kernel<<<blocks, threads, 0, 0>>>(rgb2);
    splat_metric_kernel<<<blocks, threads, 0, 0>>>(rgb1, flow_t, flow12, out_metric);
    normalize_kernel<<<blocks, threads, 0, 0>>>(out_img);
}